// round 14
// baseline (speedup 1.0000x reference)
#include <cuda_runtime.h>
#include <cuda_fp16.h>
#include <cstdint>
#include <math.h>

#define N_NODES 50000
#define N_EDGES 625000
#define N_GRAPHS 256
#define CH 128
#define N_OUT 10
#define CAP 96

// ---------------- scratch (no allocations allowed) ----------------
__device__ __half g_xh[N_NODES * CH];
__device__ __half g_z [N_NODES * CH];
__device__ __half g_h [N_NODES * CH];
__device__ __half g_Wh[9 * CH * CH];   // fp16, transposed [n][k]

__device__ int   g_cursor[N_NODES];
__device__ int   g_csrsrc[N_NODES * CAP];

// ---------------- fused prep: wh transpose+cvt | xh cvt | zero cursor ------
#define WH_BLOCKS 144
#define XH_BLOCKS ((N_NODES * CH / 4 + 255) / 256)   // 6250
#define ZERO_BLOCKS ((N_NODES + 255) / 256)          // 196
#define PREP_BLOCKS (WH_BLOCKS + XH_BLOCKS + ZERO_BLOCKS)

__global__ __launch_bounds__(256) void prep_all(
    const float* __restrict__ W, __half* __restrict__ Wh,
    const float* __restrict__ x, __half* __restrict__ xh,
    int* __restrict__ cursor)
{
    int b = blockIdx.x;
    if (b < WH_BLOCKS) {
        __shared__ float tile[32][33];
        int g = b >> 4;
        int t = b & 15;
        int kt = (t & 3) * 32, nt = (t >> 2) * 32;
        int tx = threadIdx.x & 31, ty = threadIdx.x >> 5;
        const float* Wg = W + g * CH * CH;
        __half* Whg = Wh + g * CH * CH;
#pragma unroll
        for (int i = 0; i < 32; i += 8)
            tile[ty + i][tx] = Wg[(kt + ty + i) * CH + nt + tx];
        __syncthreads();
#pragma unroll
        for (int i = 0; i < 32; i += 8)
            Whg[(nt + ty + i) * CH + kt + tx] = __float2half_rn(tile[tx][ty + i]);
    } else if (b < WH_BLOCKS + XH_BLOCKS) {
        int i = (b - WH_BLOCKS) * 256 + threadIdx.x;
        if (i < (N_NODES * CH) / 4) {
            float4 v = *(const float4*)(x + (size_t)i * 4);
            __half2 h0 = __floats2half2_rn(v.x, v.y);
            __half2 h1 = __floats2half2_rn(v.z, v.w);
            uint2 o;
            o.x = *(uint32_t*)&h0;
            o.y = *(uint32_t*)&h1;
            *(uint2*)(xh + (size_t)i * 4) = o;
        }
    } else {
        int i = (b - WH_BLOCKS - XH_BLOCKS) * 256 + threadIdx.x;
        if (i < N_NODES) cursor[i] = 0;
    }
}

// ---------------- bucket scatter ----------------
__global__ void scatter_edges(const int* __restrict__ src, const int* __restrict__ dst,
                              int* __restrict__ cursor, int* __restrict__ csrsrc) {
    int e = blockIdx.x * blockDim.x + threadIdx.x;
    if (e >= N_EDGES) return;
    int d = dst[e];
    int slot = atomicAdd(&cursor[d], 1);
    if (slot < CAP) csrsrc[d * CAP + slot] = src[e];
}

// ---------------- aggregation: shfl-broadcast indices, MLP=4 ---------------
__device__ __forceinline__ void acc_add(float2& a0, float2& a1, uint2 w) {
    float2 u0 = __half22float2(*(__half2*)&w.x);
    float2 u1 = __half22float2(*(__half2*)&w.y);
    a0.x += u0.x; a0.y += u0.y; a1.x += u1.x; a1.y += u1.y;
}

__global__ void agg_kernel(const __half* __restrict__ h, __half* __restrict__ z,
                           const int* __restrict__ cursor, const int* __restrict__ csrsrc) {
    int warp = (blockIdx.x * blockDim.x + threadIdx.x) >> 5;
    int lane = threadIdx.x & 31;
    if (warp >= N_NODES) return;
    const uint2* hv = (const uint2*)h;
    uint2 sv = hv[(size_t)warp * 32 + lane];
    float2 aA0 = __half22float2(*(__half2*)&sv.x);
    float2 aA1 = __half22float2(*(__half2*)&sv.y);
    float2 aB0 = make_float2(0.f, 0.f), aB1 = make_float2(0.f, 0.f);

    int deg = cursor[warp];
    if (deg > CAP) deg = CAP;
    const int* lst = csrsrc + warp * CAP;

    // each lane holds one neighbor index; loop body has no index-load latency
    int n32 = (deg < 32) ? deg : 32;
    int myIdx = (lane < n32) ? lst[lane] : 0;

    int i = 0;
    for (; i + 3 < n32; i += 4) {
        int i0 = __shfl_sync(0xffffffffu, myIdx, i);
        int i1 = __shfl_sync(0xffffffffu, myIdx, i + 1);
        int i2 = __shfl_sync(0xffffffffu, myIdx, i + 2);
        int i3 = __shfl_sync(0xffffffffu, myIdx, i + 3);
        uint2 w0 = hv[(size_t)i0 * 32 + lane];
        uint2 w1 = hv[(size_t)i1 * 32 + lane];
        uint2 w2 = hv[(size_t)i2 * 32 + lane];
        uint2 w3 = hv[(size_t)i3 * 32 + lane];
        acc_add(aA0, aA1, w0);
        acc_add(aB0, aB1, w1);
        acc_add(aA0, aA1, w2);
        acc_add(aB0, aB1, w3);
    }
    for (; i < n32; i++) {
        int ii = __shfl_sync(0xffffffffu, myIdx, i);
        uint2 w = hv[(size_t)ii * 32 + lane];
        acc_add(aA0, aA1, w);
    }
    for (int j = 32; j < deg; j++) {   // extremely rare (deg > 32)
        int ii = lst[j];
        uint2 w = hv[(size_t)ii * 32 + lane];
        acc_add(aB0, aB1, w);
    }

    aA0.x += aB0.x; aA0.y += aB0.y; aA1.x += aB1.x; aA1.y += aB1.y;
    __half2 o0 = __floats2half2_rn(aA0.x, aA0.y);
    __half2 o1 = __floats2half2_rn(aA1.x, aA1.y);
    uint2 o;
    o.x = *(uint32_t*)&o0;
    o.y = *(uint32_t*)&o1;
    ((uint2*)z)[(size_t)warp * 32 + lane] = o;
}

// ---------------- fused 3-layer MLP (act ping-pong + single W, 3 CTA/SM) ---
#define HS 136
#define ACT_SZ (64 * HS)
#define WB_SZ  (128 * HS)
#define MLP_SMEM ((2 * ACT_SZ + WB_SZ) * 2)   // 69632 B -> 3 CTAs/SM

__device__ __forceinline__ void mma16816(float* d, uint32_t a0, uint32_t a1,
                                         uint32_t a2, uint32_t a3,
                                         uint32_t b0, uint32_t b1) {
    asm volatile(
        "mma.sync.aligned.m16n8k16.row.col.f32.f16.f16.f32 "
        "{%0,%1,%2,%3}, {%4,%5,%6,%7}, {%8,%9}, {%0,%1,%2,%3};"
        : "+f"(d[0]), "+f"(d[1]), "+f"(d[2]), "+f"(d[3])
        : "r"(a0), "r"(a1), "r"(a2), "r"(a3), "r"(b0), "r"(b1));
}

__device__ __forceinline__ void ldsm_x4(uint32_t& r0, uint32_t& r1, uint32_t& r2,
                                        uint32_t& r3, uint32_t addr) {
    asm volatile("ldmatrix.sync.aligned.m8n8.x4.shared.b16 {%0,%1,%2,%3}, [%4];"
        : "=r"(r0), "=r"(r1), "=r"(r2), "=r"(r3) : "r"(addr));
}

__device__ __forceinline__ void cp_async16(uint32_t saddr, const void* gptr, int src_sz) {
    asm volatile("cp.async.cg.shared.global [%0], [%1], 16, %2;"
        :: "r"(saddr), "l"(gptr), "r"(src_sz));
}

__global__ __launch_bounds__(256, 3) void gin_mlp(
    const __half* __restrict__ A, const __half* __restrict__ Wh3,
    const float* __restrict__ bias3,
    __half* __restrict__ C, int M)
{
    extern __shared__ __align__(16) char smem[];
    __half* actBuf = (__half*)smem;                 // [2][64][HS]
    __half* wBuf   = actBuf + 2 * ACT_SZ;           // [128][HS]

    int tid = threadIdx.x;
    int row0 = blockIdx.x * 64;

    uint32_t actB = (uint32_t)__cvta_generic_to_shared(actBuf);
    uint32_t wB   = (uint32_t)__cvta_generic_to_shared(wBuf);

#pragma unroll
    for (int it = 0; it < 4; it++) {
        int q = tid + it * 256;
        int r = q >> 4, k8 = q & 15;
        int gr = row0 + r;
        cp_async16(actB + ((r * HS + k8 * 8) << 1),
                   A + (size_t)gr * 128 + k8 * 8, (gr < M) ? 16 : 0);
    }
#pragma unroll
    for (int it = 0; it < 8; it++) {
        int q = tid + it * 256;
        int n = q >> 4, k8 = q & 15;
        cp_async16(wB + ((n * HS + k8 * 8) << 1),
                   Wh3 + (size_t)n * 128 + k8 * 8, 16);
    }
    asm volatile("cp.async.commit_group;");
    asm volatile("cp.async.wait_group 0;");
    __syncthreads();

    int lane = tid & 31, w = tid >> 5;
    int wm = w >> 2, wn = w & 3;
    int m0 = wm * 32, n0 = wn * 32;
    int grp = lane >> 2, tig = lane & 3;

    uint32_t aPat[2], bAddr[2];
#pragma unroll
    for (int mt = 0; mt < 2; mt++)
        aPat[mt] = (uint32_t)((m0 + mt * 16 + (lane & 15)) * HS + (lane >> 4) * 8);
#pragma unroll
    for (int jj = 0; jj < 2; jj++)
        bAddr[jj] = wB + (((n0 + jj * 16 + (lane & 7) + ((lane >> 4) << 3)) * HS +
                           ((lane >> 3) & 1) * 8) << 1);

#pragma unroll
    for (int l = 0; l < 3; l++) {
        uint32_t aBase = actB + ((l & 1) ? (ACT_SZ << 1) : 0);

        float acc[2][4][4];
#pragma unroll
        for (int mt = 0; mt < 2; mt++)
#pragma unroll
            for (int j = 0; j < 4; j++)
#pragma unroll
                for (int i = 0; i < 4; i++) acc[mt][j][i] = 0.0f;

#pragma unroll
        for (int ks = 0; ks < 8; ks++) {
            uint32_t af[2][4];
#pragma unroll
            for (int mt = 0; mt < 2; mt++)
                ldsm_x4(af[mt][0], af[mt][1], af[mt][2], af[mt][3],
                        aBase + (aPat[mt] << 1) + ks * 32);
#pragma unroll
            for (int jj = 0; jj < 2; jj++) {
                uint32_t b0, b1, b2, b3;
                ldsm_x4(b0, b1, b2, b3, bAddr[jj] + ks * 32);
                mma16816(acc[0][jj * 2],     af[0][0], af[0][1], af[0][2], af[0][3], b0, b1);
                mma16816(acc[1][jj * 2],     af[1][0], af[1][1], af[1][2], af[1][3], b0, b1);
                mma16816(acc[0][jj * 2 + 1], af[0][0], af[0][1], af[0][2], af[0][3], b2, b3);
                mma16816(acc[1][jj * 2 + 1], af[1][0], af[1][1], af[1][2], af[1][3], b2, b3);
            }
        }

        const float* bias = bias3 + l * CH;
        if (l < 2) {
            __syncthreads();   // all act + W reads done
#pragma unroll
            for (int it = 0; it < 8; it++) {
                int q = tid + it * 256;
                int n = q >> 4, k8 = q & 15;
                cp_async16(wB + ((n * HS + k8 * 8) << 1),
                           Wh3 + (size_t)(l + 1) * CH * CH + (size_t)n * 128 + k8 * 8, 16);
            }
            asm volatile("cp.async.commit_group;");
            __half* actN = actBuf + ((l & 1) ? 0 : ACT_SZ);
#pragma unroll
            for (int mt = 0; mt < 2; mt++) {
                int rloc = m0 + mt * 16 + grp;
#pragma unroll
                for (int j = 0; j < 4; j++) {
                    int c = n0 + (j >> 1) * 16 + (j & 1) * 8 + tig * 2;
                    float bx = __ldg(bias + c), by = __ldg(bias + c + 1);
                    float v0 = fmaxf(acc[mt][j][0] + bx, 0.f);
                    float v1 = fmaxf(acc[mt][j][1] + by, 0.f);
                    float v2 = fmaxf(acc[mt][j][2] + bx, 0.f);
                    float v3 = fmaxf(acc[mt][j][3] + by, 0.f);
                    *(__half2*)(actN + rloc * HS + c)       = __floats2half2_rn(v0, v1);
                    *(__half2*)(actN + (rloc + 8) * HS + c) = __floats2half2_rn(v2, v3);
                }
            }
            asm volatile("cp.async.wait_group 0;");
            __syncthreads();
        } else {
#pragma unroll
            for (int mt = 0; mt < 2; mt++) {
                int r = row0 + m0 + mt * 16 + grp;
#pragma unroll
                for (int j = 0; j < 4; j++) {
                    int c = n0 + (j >> 1) * 16 + (j & 1) * 8 + tig * 2;
                    float bx = __ldg(bias + c), by = __ldg(bias + c + 1);
                    if (r < M)
                        *(__half2*)(C + (size_t)r * 128 + c) =
                            __floats2half2_rn(acc[mt][j][0] + bx, acc[mt][j][1] + by);
                    if (r + 8 < M)
                        *(__half2*)(C + (size_t)(r + 8) * 128 + c) =
                            __floats2half2_rn(acc[mt][j][2] + bx, acc[mt][j][3] + by);
                }
            }
        }
    }
}

// ---------------- fused pool (sorted segments) + head ----------------------
__global__ void pool_head(const __half* __restrict__ h, const int* __restrict__ gid,
                          const float* __restrict__ W1, const float* __restrict__ b1,
                          const float* __restrict__ W2, const float* __restrict__ b2,
                          float* __restrict__ out) {
    int g = blockIdx.x;
    int t = threadIdx.x;
    __shared__ float p[128];
    __shared__ float h1[128];
    __shared__ float logits[N_OUT];

    int lo = 0, hi = N_NODES;
    while (lo < hi) { int mid = (lo + hi) >> 1; if (gid[mid] < g) lo = mid + 1; else hi = mid; }
    int start = lo;
    lo = start; hi = N_NODES;
    while (lo < hi) { int mid = (lo + hi) >> 1; if (gid[mid] < g + 1) lo = mid + 1; else hi = mid; }
    int end = lo;

    float s = 0.0f;
#pragma unroll 4
    for (int n = start; n < end; n++)
        s += __half2float(h[(size_t)n * 128 + t]);
    int cnt = end - start;
    p[t] = s / fmaxf((float)cnt, 1.0f);
    __syncthreads();

    float acc = b1[t];
#pragma unroll 8
    for (int k = 0; k < 128; k++) acc += p[k] * W1[k * 128 + t];
    h1[t] = fmaxf(acc, 0.0f);
    __syncthreads();

    if (t < N_OUT) {
        float a = b2[t];
#pragma unroll 8
        for (int k = 0; k < 128; k++) a += h1[k] * W2[k * N_OUT + t];
        logits[t] = a;
    }
    __syncthreads();

    if (t == 0) {
        float m = -1e30f;
#pragma unroll
        for (int o = 0; o < N_OUT; o++) m = fmaxf(m, logits[o]);
        float e[N_OUT], sum = 0.0f;
#pragma unroll
        for (int o = 0; o < N_OUT; o++) { e[o] = __expf(logits[o] - m); sum += e[o]; }
        float inv = 1.0f / sum;
#pragma unroll
        for (int o = 0; o < N_OUT; o++) out[g * N_OUT + o] = e[o] * inv;
    }
}

// ---------------- launch ----------------
extern "C" void kernel_launch(void* const* d_in, const int* in_sizes, int n_in,
                              void* d_out, int out_size) {
    const float* x        = (const float*)d_in[0];
    const int*   edge_src = (const int*)  d_in[1];
    const int*   edge_dst = (const int*)  d_in[2];
    const int*   graph_id = (const int*)  d_in[3];
    const float* conv_W   = (const float*)d_in[4];
    const float* conv_b   = (const float*)d_in[5];
    const float* d1_W     = (const float*)d_in[6];
    const float* d1_b     = (const float*)d_in[7];
    const float* d2_W     = (const float*)d_in[8];
    const float* d2_b     = (const float*)d_in[9];
    float* out = (float*)d_out;

    __half *xh, *z, *h, *Wh;
    int *cursor, *csrsrc;
    cudaGetSymbolAddress((void**)&xh,     g_xh);
    cudaGetSymbolAddress((void**)&z,      g_z);
    cudaGetSymbolAddress((void**)&h,      g_h);
    cudaGetSymbolAddress((void**)&Wh,     g_Wh);
    cudaGetSymbolAddress((void**)&cursor, g_cursor);
    cudaGetSymbolAddress((void**)&csrsrc, g_csrsrc);

    cudaFuncSetAttribute(gin_mlp, cudaFuncAttributeMaxDynamicSharedMemorySize, MLP_SMEM);

    const int TB = 256;
    const int aggBlocks = (N_NODES * 32 + TB - 1) / TB;
    const int mlpBlocks = (N_NODES + 63) / 64;      // 782

    prep_all<<<PREP_BLOCKS, 256>>>(conv_W, Wh, x, xh, cursor);
    scatter_edges<<<(N_EDGES + TB - 1) / TB, TB>>>(edge_src, edge_dst, cursor, csrsrc);

    const __half* hin = xh;
    for (int l = 0; l < 3; l++) {
        agg_kernel<<<aggBlocks, TB>>>(hin, z, cursor, csrsrc);
        gin_mlp<<<mlpBlocks, 256, MLP_SMEM>>>(z,
            Wh + (size_t)l * 3 * CH * CH, conv_b + (size_t)l * 3 * CH, h, N_NODES);
        hin = h;
    }

    pool_head<<<N_GRAPHS, 128>>>(h, graph_id, d1_W, d1_b, d2_W, d2_b, out);
}

// round 15
// speedup vs baseline: 1.0240x; 1.0240x over previous
#include <cuda_runtime.h>
#include <cuda_fp16.h>
#include <cstdint>
#include <math.h>

#define N_NODES 50000
#define N_EDGES 625000
#define N_GRAPHS 256
#define CH 128
#define N_OUT 10
#define CAP 96

// ---------------- scratch (no allocations allowed) ----------------
__device__ __half g_xh[N_NODES * CH];
__device__ __half g_z [N_NODES * CH];
__device__ __half g_h [N_NODES * CH];
__device__ __half g_Wh[9 * CH * CH];   // fp16, transposed [n][k]

__device__ int   g_cursor[N_NODES];
__device__ int   g_csrsrc[N_NODES * CAP];

// ---------------- fused prep: wh transpose+cvt | xh cvt | zero cursor ------
#define WH_BLOCKS 144
#define XH_BLOCKS ((N_NODES * CH / 4 + 255) / 256)   // 6250
#define ZERO_BLOCKS ((N_NODES + 255) / 256)          // 196
#define PREP_BLOCKS (WH_BLOCKS + XH_BLOCKS + ZERO_BLOCKS)

__global__ __launch_bounds__(256) void prep_all(
    const float* __restrict__ W, __half* __restrict__ Wh,
    const float* __restrict__ x, __half* __restrict__ xh,
    int* __restrict__ cursor)
{
    int b = blockIdx.x;
    if (b < WH_BLOCKS) {
        __shared__ float tile[32][33];
        int g = b >> 4;
        int t = b & 15;
        int kt = (t & 3) * 32, nt = (t >> 2) * 32;
        int tx = threadIdx.x & 31, ty = threadIdx.x >> 5;
        const float* Wg = W + g * CH * CH;
        __half* Whg = Wh + g * CH * CH;
#pragma unroll
        for (int i = 0; i < 32; i += 8)
            tile[ty + i][tx] = Wg[(kt + ty + i) * CH + nt + tx];
        __syncthreads();
#pragma unroll
        for (int i = 0; i < 32; i += 8)
            Whg[(nt + ty + i) * CH + kt + tx] = __float2half_rn(tile[tx][ty + i]);
    } else if (b < WH_BLOCKS + XH_BLOCKS) {
        int i = (b - WH_BLOCKS) * 256 + threadIdx.x;
        if (i < (N_NODES * CH) / 4) {
            float4 v = *(const float4*)(x + (size_t)i * 4);
            __half2 h0 = __floats2half2_rn(v.x, v.y);
            __half2 h1 = __floats2half2_rn(v.z, v.w);
            uint2 o;
            o.x = *(uint32_t*)&h0;
            o.y = *(uint32_t*)&h1;
            *(uint2*)(xh + (size_t)i * 4) = o;
        }
    } else {
        int i = (b - WH_BLOCKS - XH_BLOCKS) * 256 + threadIdx.x;
        if (i < N_NODES) cursor[i] = 0;
    }
}

// ---------------- bucket scatter ----------------
__global__ void scatter_edges(const int* __restrict__ src, const int* __restrict__ dst,
                              int* __restrict__ cursor, int* __restrict__ csrsrc) {
    int e = blockIdx.x * blockDim.x + threadIdx.x;
    if (e >= N_EDGES) return;
    int d = dst[e];
    int slot = atomicAdd(&cursor[d], 1);
    if (slot < CAP) csrsrc[d * CAP + slot] = src[e];
}

// ---------------- aggregation: half-warp per node, LDG.128 -----------------
// 16 lanes x uint4 (8 halves) = one 256B row per half-warp per load.
__device__ __forceinline__ void acc_add4(float* a, uint4 w) {
    float2 u0 = __half22float2(*(__half2*)&w.x);
    float2 u1 = __half22float2(*(__half2*)&w.y);
    float2 u2 = __half22float2(*(__half2*)&w.z);
    float2 u3 = __half22float2(*(__half2*)&w.w);
    a[0] += u0.x; a[1] += u0.y; a[2] += u1.x; a[3] += u1.y;
    a[4] += u2.x; a[5] += u2.y; a[6] += u3.x; a[7] += u3.y;
}

__global__ void agg_kernel(const __half* __restrict__ h, __half* __restrict__ z,
                           const int* __restrict__ cursor, const int* __restrict__ csrsrc) {
    int node = (blockIdx.x * blockDim.x + threadIdx.x) >> 4;   // half-warp per node
    int lane = threadIdx.x & 15;
    if (node >= N_NODES) return;
    const uint4* hv = (const uint4*)h;   // 16 uint4 per row

    float acc[8];
    {
        uint4 sv = hv[(size_t)node * 16 + lane];
#pragma unroll
        for (int q = 0; q < 8; q++) acc[q] = 0.f;
        acc_add4(acc, sv);
    }

    int deg = cursor[node];
    if (deg > CAP) deg = CAP;
    const int* lst = csrsrc + node * CAP;

    int i = 0;
    for (; i + 1 < deg; i += 2) {
        int s0 = lst[i], s1 = lst[i + 1];
        uint4 w0 = hv[(size_t)s0 * 16 + lane];
        uint4 w1 = hv[(size_t)s1 * 16 + lane];
        acc_add4(acc, w0);
        acc_add4(acc, w1);
    }
    if (i < deg) {
        int s0 = lst[i];
        uint4 w0 = hv[(size_t)s0 * 16 + lane];
        acc_add4(acc, w0);
    }

    __half2 o0 = __floats2half2_rn(acc[0], acc[1]);
    __half2 o1 = __floats2half2_rn(acc[2], acc[3]);
    __half2 o2 = __floats2half2_rn(acc[4], acc[5]);
    __half2 o3 = __floats2half2_rn(acc[6], acc[7]);
    uint4 o;
    o.x = *(uint32_t*)&o0;
    o.y = *(uint32_t*)&o1;
    o.z = *(uint32_t*)&o2;
    o.w = *(uint32_t*)&o3;
    ((uint4*)z)[(size_t)node * 16 + lane] = o;
}

// ---------------- fused 3-layer MLP (act ping-pong + single W, 3 CTA/SM) ---
#define HS 136
#define ACT_SZ (64 * HS)
#define WB_SZ  (128 * HS)
#define MLP_SMEM ((2 * ACT_SZ + WB_SZ) * 2)   // 69632 B -> 3 CTAs/SM

__device__ __forceinline__ void mma16816(float* d, uint32_t a0, uint32_t a1,
                                         uint32_t a2, uint32_t a3,
                                         uint32_t b0, uint32_t b1) {
    asm volatile(
        "mma.sync.aligned.m16n8k16.row.col.f32.f16.f16.f32 "
        "{%0,%1,%2,%3}, {%4,%5,%6,%7}, {%8,%9}, {%0,%1,%2,%3};"
        : "+f"(d[0]), "+f"(d[1]), "+f"(d[2]), "+f"(d[3])
        : "r"(a0), "r"(a1), "r"(a2), "r"(a3), "r"(b0), "r"(b1));
}

__device__ __forceinline__ void ldsm_x4(uint32_t& r0, uint32_t& r1, uint32_t& r2,
                                        uint32_t& r3, uint32_t addr) {
    asm volatile("ldmatrix.sync.aligned.m8n8.x4.shared.b16 {%0,%1,%2,%3}, [%4];"
        : "=r"(r0), "=r"(r1), "=r"(r2), "=r"(r3) : "r"(addr));
}

__device__ __forceinline__ void cp_async16(uint32_t saddr, const void* gptr, int src_sz) {
    asm volatile("cp.async.cg.shared.global [%0], [%1], 16, %2;"
        :: "r"(saddr), "l"(gptr), "r"(src_sz));
}

__global__ __launch_bounds__(256, 3) void gin_mlp(
    const __half* __restrict__ A, const __half* __restrict__ Wh3,
    const float* __restrict__ bias3,
    __half* __restrict__ C, int M)
{
    extern __shared__ __align__(16) char smem[];
    __half* actBuf = (__half*)smem;                 // [2][64][HS]
    __half* wBuf   = actBuf + 2 * ACT_SZ;           // [128][HS]

    int tid = threadIdx.x;
    int row0 = blockIdx.x * 64;

    uint32_t actB = (uint32_t)__cvta_generic_to_shared(actBuf);
    uint32_t wB   = (uint32_t)__cvta_generic_to_shared(wBuf);

#pragma unroll
    for (int it = 0; it < 4; it++) {
        int q = tid + it * 256;
        int r = q >> 4, k8 = q & 15;
        int gr = row0 + r;
        cp_async16(actB + ((r * HS + k8 * 8) << 1),
                   A + (size_t)gr * 128 + k8 * 8, (gr < M) ? 16 : 0);
    }
#pragma unroll
    for (int it = 0; it < 8; it++) {
        int q = tid + it * 256;
        int n = q >> 4, k8 = q & 15;
        cp_async16(wB + ((n * HS + k8 * 8) << 1),
                   Wh3 + (size_t)n * 128 + k8 * 8, 16);
    }
    asm volatile("cp.async.commit_group;");
    asm volatile("cp.async.wait_group 0;");
    __syncthreads();

    int lane = tid & 31, w = tid >> 5;
    int wm = w >> 2, wn = w & 3;
    int m0 = wm * 32, n0 = wn * 32;
    int grp = lane >> 2, tig = lane & 3;

    uint32_t aPat[2], bAddr[2];
#pragma unroll
    for (int mt = 0; mt < 2; mt++)
        aPat[mt] = (uint32_t)((m0 + mt * 16 + (lane & 15)) * HS + (lane >> 4) * 8);
#pragma unroll
    for (int jj = 0; jj < 2; jj++)
        bAddr[jj] = wB + (((n0 + jj * 16 + (lane & 7) + ((lane >> 4) << 3)) * HS +
                           ((lane >> 3) & 1) * 8) << 1);

#pragma unroll
    for (int l = 0; l < 3; l++) {
        uint32_t aBase = actB + ((l & 1) ? (ACT_SZ << 1) : 0);

        float acc[2][4][4];
#pragma unroll
        for (int mt = 0; mt < 2; mt++)
#pragma unroll
            for (int j = 0; j < 4; j++)
#pragma unroll
                for (int i = 0; i < 4; i++) acc[mt][j][i] = 0.0f;

#pragma unroll
        for (int ks = 0; ks < 8; ks++) {
            uint32_t af[2][4];
#pragma unroll
            for (int mt = 0; mt < 2; mt++)
                ldsm_x4(af[mt][0], af[mt][1], af[mt][2], af[mt][3],
                        aBase + (aPat[mt] << 1) + ks * 32);
#pragma unroll
            for (int jj = 0; jj < 2; jj++) {
                uint32_t b0, b1, b2, b3;
                ldsm_x4(b0, b1, b2, b3, bAddr[jj] + ks * 32);
                mma16816(acc[0][jj * 2],     af[0][0], af[0][1], af[0][2], af[0][3], b0, b1);
                mma16816(acc[1][jj * 2],     af[1][0], af[1][1], af[1][2], af[1][3], b0, b1);
                mma16816(acc[0][jj * 2 + 1], af[0][0], af[0][1], af[0][2], af[0][3], b2, b3);
                mma16816(acc[1][jj * 2 + 1], af[1][0], af[1][1], af[1][2], af[1][3], b2, b3);
            }
        }

        const float* bias = bias3 + l * CH;
        if (l < 2) {
            __syncthreads();   // all act + W reads done
#pragma unroll
            for (int it = 0; it < 8; it++) {
                int q = tid + it * 256;
                int n = q >> 4, k8 = q & 15;
                cp_async16(wB + ((n * HS + k8 * 8) << 1),
                           Wh3 + (size_t)(l + 1) * CH * CH + (size_t)n * 128 + k8 * 8, 16);
            }
            asm volatile("cp.async.commit_group;");
            __half* actN = actBuf + ((l & 1) ? 0 : ACT_SZ);
#pragma unroll
            for (int mt = 0; mt < 2; mt++) {
                int rloc = m0 + mt * 16 + grp;
#pragma unroll
                for (int j = 0; j < 4; j++) {
                    int c = n0 + (j >> 1) * 16 + (j & 1) * 8 + tig * 2;
                    float bx = __ldg(bias + c), by = __ldg(bias + c + 1);
                    float v0 = fmaxf(acc[mt][j][0] + bx, 0.f);
                    float v1 = fmaxf(acc[mt][j][1] + by, 0.f);
                    float v2 = fmaxf(acc[mt][j][2] + bx, 0.f);
                    float v3 = fmaxf(acc[mt][j][3] + by, 0.f);
                    *(__half2*)(actN + rloc * HS + c)       = __floats2half2_rn(v0, v1);
                    *(__half2*)(actN + (rloc + 8) * HS + c) = __floats2half2_rn(v2, v3);
                }
            }
            asm volatile("cp.async.wait_group 0;");
            __syncthreads();
        } else {
#pragma unroll
            for (int mt = 0; mt < 2; mt++) {
                int r = row0 + m0 + mt * 16 + grp;
#pragma unroll
                for (int j = 0; j < 4; j++) {
                    int c = n0 + (j >> 1) * 16 + (j & 1) * 8 + tig * 2;
                    float bx = __ldg(bias + c), by = __ldg(bias + c + 1);
                    if (r < M)
                        *(__half2*)(C + (size_t)r * 128 + c) =
                            __floats2half2_rn(acc[mt][j][0] + bx, acc[mt][j][1] + by);
                    if (r + 8 < M)
                        *(__half2*)(C + (size_t)(r + 8) * 128 + c) =
                            __floats2half2_rn(acc[mt][j][2] + bx, acc[mt][j][3] + by);
                }
            }
        }
    }
}

// ---------------- fused pool (sorted segments) + head ----------------------
__global__ void pool_head(const __half* __restrict__ h, const int* __restrict__ gid,
                          const float* __restrict__ W1, const float* __restrict__ b1,
                          const float* __restrict__ W2, const float* __restrict__ b2,
                          float* __restrict__ out) {
    int g = blockIdx.x;
    int t = threadIdx.x;
    __shared__ float p[128];
    __shared__ float h1[128];
    __shared__ float logits[N_OUT];

    int lo = 0, hi = N_NODES;
    while (lo < hi) { int mid = (lo + hi) >> 1; if (gid[mid] < g) lo = mid + 1; else hi = mid; }
    int start = lo;
    lo = start; hi = N_NODES;
    while (lo < hi) { int mid = (lo + hi) >> 1; if (gid[mid] < g + 1) lo = mid + 1; else hi = mid; }
    int end = lo;

    float s = 0.0f;
#pragma unroll 4
    for (int n = start; n < end; n++)
        s += __half2float(h[(size_t)n * 128 + t]);
    int cnt = end - start;
    p[t] = s / fmaxf((float)cnt, 1.0f);
    __syncthreads();

    float acc = b1[t];
#pragma unroll 8
    for (int k = 0; k < 128; k++) acc += p[k] * W1[k * 128 + t];
    h1[t] = fmaxf(acc, 0.0f);
    __syncthreads();

    if (t < N_OUT) {
        float a = b2[t];
#pragma unroll 8
        for (int k = 0; k < 128; k++) a += h1[k] * W2[k * N_OUT + t];
        logits[t] = a;
    }
    __syncthreads();

    if (t == 0) {
        float m = -1e30f;
#pragma unroll
        for (int o = 0; o < N_OUT; o++) m = fmaxf(m, logits[o]);
        float e[N_OUT], sum = 0.0f;
#pragma unroll
        for (int o = 0; o < N_OUT; o++) { e[o] = __expf(logits[o] - m); sum += e[o]; }
        float inv = 1.0f / sum;
#pragma unroll
        for (int o = 0; o < N_OUT; o++) out[g * N_OUT + o] = e[o] * inv;
    }
}

// ---------------- launch ----------------
extern "C" void kernel_launch(void* const* d_in, const int* in_sizes, int n_in,
                              void* d_out, int out_size) {
    const float* x        = (const float*)d_in[0];
    const int*   edge_src = (const int*)  d_in[1];
    const int*   edge_dst = (const int*)  d_in[2];
    const int*   graph_id = (const int*)  d_in[3];
    const float* conv_W   = (const float*)d_in[4];
    const float* conv_b   = (const float*)d_in[5];
    const float* d1_W     = (const float*)d_in[6];
    const float* d1_b     = (const float*)d_in[7];
    const float* d2_W     = (const float*)d_in[8];
    const float* d2_b     = (const float*)d_in[9];
    float* out = (float*)d_out;

    __half *xh, *z, *h, *Wh;
    int *cursor, *csrsrc;
    cudaGetSymbolAddress((void**)&xh,     g_xh);
    cudaGetSymbolAddress((void**)&z,      g_z);
    cudaGetSymbolAddress((void**)&h,      g_h);
    cudaGetSymbolAddress((void**)&Wh,     g_Wh);
    cudaGetSymbolAddress((void**)&cursor, g_cursor);
    cudaGetSymbolAddress((void**)&csrsrc, g_csrsrc);

    cudaFuncSetAttribute(gin_mlp, cudaFuncAttributeMaxDynamicSharedMemorySize, MLP_SMEM);

    const int TB = 256;
    const int aggBlocks = (N_NODES * 16 + TB - 1) / TB;   // half-warp per node
    const int mlpBlocks = (N_NODES + 63) / 64;            // 782

    prep_all<<<PREP_BLOCKS, 256>>>(conv_W, Wh, x, xh, cursor);
    scatter_edges<<<(N_EDGES + TB - 1) / TB, TB>>>(edge_src, edge_dst, cursor, csrsrc);

    const __half* hin = xh;
    for (int l = 0; l < 3; l++) {
        agg_kernel<<<aggBlocks, TB>>>(hin, z, cursor, csrsrc);
        gin_mlp<<<mlpBlocks, 256, MLP_SMEM>>>(z,
            Wh + (size_t)l * 3 * CH * CH, conv_b + (size_t)l * 3 * CH, h, N_NODES);
        hin = h;
    }

    pool_head<<<N_GRAPHS, 128>>>(h, graph_id, d1_W, d1_b, d2_W, d2_b, out);
}